// round 2
// baseline (speedup 1.0000x reference)
#include <cuda_runtime.h>
#include <cuda_bf16.h>

// ---------------------------------------------------------------------------
// GCN: 3x (scale -> GEMM -> edge scatter-sum -> scale+bias(+relu)) + mean pool
// Rewritten as: X = f(prev)@W  (GEMM first), then scatter-add X[src] -> AGG[dst]
// since row-scaling commutes with @W and segment-sum is linear.
// ---------------------------------------------------------------------------

#define MAX_NODES 100000
#define MAX_FEATS 128

__device__ float g_X[MAX_NODES * MAX_FEATS];    // GEMM outputs (pre-scatter)
__device__ float g_AGG[MAX_NODES * MAX_FEATS];  // scatter accumulators
__device__ float g_outnorm[MAX_NODES];          // deg_out -> rsqrt
__device__ float g_innorm[MAX_NODES];           // deg_in  -> rsqrt

// ---------------------------- utility kernels ------------------------------

__global__ void zero_kernel(float* __restrict__ p, int n4) {
    int i = blockIdx.x * blockDim.x + threadIdx.x;
    if (i < n4) reinterpret_cast<float4*>(p)[i] = make_float4(0.f, 0.f, 0.f, 0.f);
}

__global__ void degree_kernel(const int* __restrict__ src, const int* __restrict__ dst,
                              float* __restrict__ od, float* __restrict__ id, int E) {
    int i = blockIdx.x * blockDim.x + threadIdx.x;
    if (i < E) {
        atomicAdd(od + src[i], 1.0f);
        atomicAdd(id + dst[i], 1.0f);
    }
}

__global__ void norm_kernel(float* __restrict__ od, float* __restrict__ id, int n) {
    int i = blockIdx.x * blockDim.x + threadIdx.x;
    if (i < n) {
        od[i] = rsqrtf(fmaxf(od[i], 1.0f));
        id[i] = rsqrtf(fmaxf(id[i], 1.0f));
    }
}

// ------------------------------- GEMM --------------------------------------
// X[M,N] = f(A[M,K]) @ W[K,N]
// MODE 0: f(a)[r,k] = a[r,k] * outnorm[r]                      (layer 1 input)
// MODE 1: f(a)[r,k] = relu(a[r,k]*innorm[r] + bprev[k]) * outnorm[r]
// BM=128 rows/block, BK=32, 256 threads, per-thread tile TM=8 x TN=(N/16).

template<int K, int N, int MODE>
__global__ __launch_bounds__(256, 2)
void gemm_kernel(const float* __restrict__ A, const float* __restrict__ W,
                 const float* __restrict__ bprev,
                 const float* __restrict__ outnorm, const float* __restrict__ innorm,
                 float* __restrict__ X, int M) {
    constexpr int BM = 128;
    constexpr int BK = 32;
    constexpr int TM = 8;
    constexpr int TN = (BM * N) / (256 * TM);   // 8 for N=128, 4 for N=64

    __shared__ float Ws[BK][N];         // W chunk, [k][n]
    __shared__ float As[BK][BM + 4];    // A chunk transposed, [k][row]

    const int tid = threadIdx.x;
    const int cg  = tid & 15;           // column group 0..15
    const int rg  = tid >> 4;           // row group    0..15
    const int row0 = blockIdx.x * BM;

    float acc[TM][TN];
#pragma unroll
    for (int i = 0; i < TM; i++)
#pragma unroll
        for (int j = 0; j < TN; j++) acc[i][j] = 0.f;

    for (int kc = 0; kc < K; kc += BK) {
        __syncthreads();
        // ---- load A chunk (transposed, with fused pointwise) ----
        // 128 rows x 32 cols = 1024 float4; thread handles 4.
#pragma unroll
        for (int jj = 0; jj < 4; jj++) {
            int i  = tid + 256 * jj;
            int rl = i >> 3;            // local row 0..127
            int kq = (i & 7) * 4;       // k-offset in chunk 0..28
            int row = row0 + rl;
            float4 v = make_float4(0.f, 0.f, 0.f, 0.f);
            if (row < M) {
                v = *reinterpret_cast<const float4*>(A + (long)row * K + kc + kq);
                if (MODE == 0) {
                    float on = outnorm[row];
                    v.x *= on; v.y *= on; v.z *= on; v.w *= on;
                } else {
                    float inn = innorm[row];
                    float on  = outnorm[row];
                    v.x = fmaxf(fmaf(v.x, inn, bprev[kc + kq + 0]), 0.f) * on;
                    v.y = fmaxf(fmaf(v.y, inn, bprev[kc + kq + 1]), 0.f) * on;
                    v.z = fmaxf(fmaf(v.z, inn, bprev[kc + kq + 2]), 0.f) * on;
                    v.w = fmaxf(fmaf(v.w, inn, bprev[kc + kq + 3]), 0.f) * on;
                }
            }
            As[kq + 0][rl] = v.x;
            As[kq + 1][rl] = v.y;
            As[kq + 2][rl] = v.z;
            As[kq + 3][rl] = v.w;
        }
        // ---- load W chunk ----
        {
            constexpr int NF4 = BK * N / 4;
            const float4* Wg = reinterpret_cast<const float4*>(W + kc * N);
            float4* Wsf = reinterpret_cast<float4*>(&Ws[0][0]);
#pragma unroll
            for (int i = tid; i < NF4; i += 256) Wsf[i] = Wg[i];
        }
        __syncthreads();
        // ---- compute ----
#pragma unroll
        for (int kk = 0; kk < BK; kk++) {
            float a[TM], w[TN];
            float4 a0 = *reinterpret_cast<const float4*>(&As[kk][rg * TM]);
            float4 a1 = *reinterpret_cast<const float4*>(&As[kk][rg * TM + 4]);
            a[0] = a0.x; a[1] = a0.y; a[2] = a0.z; a[3] = a0.w;
            a[4] = a1.x; a[5] = a1.y; a[6] = a1.z; a[7] = a1.w;
#pragma unroll
            for (int j = 0; j < TN; j += 4) {
                float4 t = *reinterpret_cast<const float4*>(&Ws[kk][cg * TN + j]);
                w[j + 0] = t.x; w[j + 1] = t.y; w[j + 2] = t.z; w[j + 3] = t.w;
            }
#pragma unroll
            for (int i = 0; i < TM; i++)
#pragma unroll
                for (int j = 0; j < TN; j++)
                    acc[i][j] = fmaf(a[i], w[j], acc[i][j]);
        }
    }
    // ---- store ----
#pragma unroll
    for (int i = 0; i < TM; i++) {
        int row = row0 + rg * TM + i;
        if (row < M) {
#pragma unroll
            for (int j = 0; j < TN; j += 4) {
                float4 t = make_float4(acc[i][j], acc[i][j + 1], acc[i][j + 2], acc[i][j + 3]);
                *reinterpret_cast<float4*>(X + (long)row * N + cg * TN + j) = t;
            }
        }
    }
}

// ------------------------------ scatter ------------------------------------
// AGG[dst[e]] += X[src[e]]  (D floats per edge), vector red.global.add.v4.f32

template<int D>
__global__ void scatter_kernel(const float* __restrict__ X,
                               const int* __restrict__ src, const int* __restrict__ dst,
                               float* __restrict__ AGG, int E) {
    constexpr int TPE = D / 4;  // threads per edge (32 for D=128, 16 for D=64)
    int t = blockIdx.x * blockDim.x + threadIdx.x;
    int e = t / TPE;
    if (e >= E) return;
    int c = (t % TPE) * 4;
    int s = __ldg(src + e);
    int d = __ldg(dst + e);
    float4 v = __ldg(reinterpret_cast<const float4*>(X + (long)s * D + c));
    float* p = AGG + (long)d * D + c;
    asm volatile("red.global.add.v4.f32 [%0], {%1, %2, %3, %4};"
                 :: "l"(p), "f"(v.x), "f"(v.y), "f"(v.z), "f"(v.w)
                 : "memory");
}

// ------------------------------- pooling -----------------------------------
// out[g, f] = mean over nodes n with gid[n]==g of (AGG[n,f]*innorm[n] + b3[f])
// graph_ids sorted -> binary search per-graph range. 64 blocks x 256 threads.

__device__ __forceinline__ int lower_bound_dev(const int* __restrict__ a, int n, int v) {
    int lo = 0, hi = n;
    while (lo < hi) {
        int m = (lo + hi) >> 1;
        if (a[m] < v) lo = m + 1; else hi = m;
    }
    return lo;
}

__global__ void pool_kernel(const float* __restrict__ AGG, const float* __restrict__ innorm,
                            const float* __restrict__ b3, const int* __restrict__ gids,
                            float* __restrict__ out, int Nn) {
    int g = blockIdx.x;
    int lo = lower_bound_dev(gids, Nn, g);
    int hi = lower_bound_dev(gids, Nn, g + 1);
    int f = threadIdx.x & 63;
    int slot = threadIdx.x >> 6;   // 0..3
    float bf = b3[f];
    float sum = 0.f;
    for (int i = lo + slot; i < hi; i += 4)
        sum += fmaf(AGG[(long)i * 64 + f], innorm[i], bf);
    __shared__ float sh[256];
    sh[threadIdx.x] = sum;
    __syncthreads();
    if (slot == 0) {
        float tot = sh[f] + sh[64 + f] + sh[128 + f] + sh[192 + f];
        float cnt = (float)(hi - lo);
        out[g * 64 + f] = tot / fmaxf(cnt, 1.f);
    }
}

// ------------------------------- launch ------------------------------------

extern "C" void kernel_launch(void* const* d_in, const int* in_sizes, int n_in,
                              void* d_out, int out_size) {
    const float* emb = (const float*)d_in[0];
    const float* W1  = (const float*)d_in[1];
    const float* b1  = (const float*)d_in[2];
    const float* W2  = (const float*)d_in[3];
    const float* b2  = (const float*)d_in[4];
    const float* W3  = (const float*)d_in[5];
    const float* b3  = (const float*)d_in[6];
    const int*   src = (const int*)d_in[7];
    const int*   dst = (const int*)d_in[8];
    const int*   gid = (const int*)d_in[9];
    float* out = (float*)d_out;

    const int Nn = in_sizes[0] / 128;   // 100000
    const int E  = in_sizes[7];         // 1600000
    const int G  = out_size / 64;       // 64

    float *X, *AGG, *onrm, *inrm;
    cudaGetSymbolAddress((void**)&X,    g_X);
    cudaGetSymbolAddress((void**)&AGG,  g_AGG);
    cudaGetSymbolAddress((void**)&onrm, g_outnorm);
    cudaGetSymbolAddress((void**)&inrm, g_innorm);

    const int T = 256;
    const int gemm_grid = (Nn + 127) / 128;

    // degrees -> norms
    zero_kernel<<<(Nn / 4 + T - 1) / T, T>>>(onrm, Nn / 4);
    zero_kernel<<<(Nn / 4 + T - 1) / T, T>>>(inrm, Nn / 4);
    degree_kernel<<<(E + T - 1) / T, T>>>(src, dst, onrm, inrm, E);
    norm_kernel<<<(Nn + T - 1) / T, T>>>(onrm, inrm, Nn);

    // Layer 1: X1 = (emb * outnorm) @ W1   [K=128,N=128]
    gemm_kernel<128, 128, 0><<<gemm_grid, T>>>(emb, W1, nullptr, onrm, inrm, X, Nn);
    zero_kernel<<<(Nn * 128 / 4 + T - 1) / T, T>>>(AGG, Nn * 128 / 4);
    scatter_kernel<128><<<((long)E * 32 + T - 1) / T, T>>>(X, src, dst, AGG, E);

    // Layer 2: X2 = relu(agg1*innorm + b1)*outnorm @ W2   [K=128,N=64]
    gemm_kernel<128, 64, 1><<<gemm_grid, T>>>(AGG, W2, b1, onrm, inrm, X, Nn);
    zero_kernel<<<(Nn * 64 / 4 + T - 1) / T, T>>>(AGG, Nn * 64 / 4);
    scatter_kernel<64><<<((long)E * 16 + T - 1) / T, T>>>(X, src, dst, AGG, E);

    // Layer 3: X3 = relu(agg2*innorm + b2)*outnorm @ W3   [K=64,N=64]
    gemm_kernel<64, 64, 1><<<gemm_grid, T>>>(AGG, W3, b2, onrm, inrm, X, Nn);
    zero_kernel<<<(Nn * 64 / 4 + T - 1) / T, T>>>(AGG, Nn * 64 / 4);
    scatter_kernel<64><<<((long)E * 16 + T - 1) / T, T>>>(X, src, dst, AGG, E);

    // Pool: out[g,f] = mean(agg3*innorm + b3)
    pool_kernel<<<G, T>>>(AGG, inrm, b3, gid, out, Nn);
}

// round 4
// speedup vs baseline: 1.0532x; 1.0532x over previous
#include <cuda_runtime.h>
#include <cuda_bf16.h>
#include <cstdint>

// ---------------------------------------------------------------------------
// GCN: 3x (pointwise -> bf16x3 mma.sync GEMM -> edge scatter-sum) + mean pool
// GEMM first (row scaling commutes with @W; segment-sum is linear), so the
// scatter runs on the smallest feature dim per layer.
// sm_100 baseline path: mma.sync + ldmatrix (tcgen05 not accepted by ptxas).
// ---------------------------------------------------------------------------

#define MAX_NODES 100000
#define MAX_FEATS 128

__device__ float g_X[MAX_NODES * MAX_FEATS];    // GEMM outputs (pre-scatter)
__device__ float g_AGG[MAX_NODES * MAX_FEATS];  // scatter accumulators
__device__ float g_outnorm[MAX_NODES];
__device__ float g_innorm[MAX_NODES];

// ----------------------------- helpers -------------------------------------

__device__ __forceinline__ uint32_t smem_u32(const void* p) {
    uint32_t a;
    asm("{ .reg .u64 t; cvta.to.shared.u64 t, %1; cvt.u32.u64 %0, t; }" : "=r"(a) : "l"(p));
    return a;
}

__device__ __forceinline__ void ldsm_x4(uint32_t* r, uint32_t addr) {
    asm volatile("ldmatrix.sync.aligned.m8n8.x4.shared.b16 {%0,%1,%2,%3}, [%4];"
                 : "=r"(r[0]), "=r"(r[1]), "=r"(r[2]), "=r"(r[3]) : "r"(addr));
}

__device__ __forceinline__ void mma_bf16(float* d, const uint32_t* a, const uint32_t* b) {
    asm volatile("mma.sync.aligned.m16n8k16.row.col.f32.bf16.bf16.f32 "
                 "{%0,%1,%2,%3}, {%4,%5,%6,%7}, {%8,%9}, {%0,%1,%2,%3};"
                 : "+f"(d[0]), "+f"(d[1]), "+f"(d[2]), "+f"(d[3])
                 : "r"(a[0]), "r"(a[1]), "r"(a[2]), "r"(a[3]), "r"(b[0]), "r"(b[1]));
}

// split two floats into packed bf16 hi pair + bf16 residual pair
__device__ __forceinline__ void split2(float x, float y, uint32_t& hi, uint32_t& lo) {
    __nv_bfloat162 h = __floats2bfloat162_rn(x, y);
    float rx = x - __bfloat162float(h.x);
    float ry = y - __bfloat162float(h.y);
    __nv_bfloat162 l = __floats2bfloat162_rn(rx, ry);
    hi = reinterpret_cast<uint32_t&>(h);
    lo = reinterpret_cast<uint32_t&>(l);
}

__device__ __forceinline__ void split1(float x, uint16_t& hi, uint16_t& lo) {
    __nv_bfloat16 h = __float2bfloat16_rn(x);
    float r = x - __bfloat162float(h);
    __nv_bfloat16 l = __float2bfloat16_rn(r);
    hi = reinterpret_cast<uint16_t&>(h);
    lo = reinterpret_cast<uint16_t&>(l);
}

// ---------------------------- utility kernels ------------------------------

__global__ void zero_kernel(float* __restrict__ p, int n4) {
    int i = blockIdx.x * blockDim.x + threadIdx.x;
    if (i < n4) reinterpret_cast<float4*>(p)[i] = make_float4(0.f, 0.f, 0.f, 0.f);
}

__global__ void degree_kernel(const int* __restrict__ src, const int* __restrict__ dst,
                              float* __restrict__ od, float* __restrict__ id, int E) {
    int i = blockIdx.x * blockDim.x + threadIdx.x;
    if (i < E) {
        atomicAdd(od + src[i], 1.0f);
        atomicAdd(id + dst[i], 1.0f);
    }
}

__global__ void norm_kernel(float* __restrict__ od, float* __restrict__ id, int n) {
    int i = blockIdx.x * blockDim.x + threadIdx.x;
    if (i < n) {
        od[i] = rsqrtf(fmaxf(od[i], 1.0f));
        id[i] = rsqrtf(fmaxf(id[i], 1.0f));
    }
}

// --------------------------- bf16x3 GEMM -----------------------------------
// X[M,N] = f(A[M,K]) @ W[K,N], CTA tile 128 x N, K chunks of 32, 256 threads.
// MODE 0: f(a)[r,k] = a[r,k] * outnorm[r]
// MODE 1: f(a)[r,k] = relu(a[r,k]*innorm[r] + bprev[k]) * outnorm[r]
// bf16x3: D = Ah@Bh + Ah@Bl + Al@Bh, fp32 accum (mma.sync m16n8k16).
// SMEM: A hi/lo [128][P], W^T hi/lo [N][P] bf16, P=40 (80B pitch, LDSM-clean),
// double buffered; global loads for chunk c+1 issued before compute(c).

template<int K, int N, int MODE>
__global__ __launch_bounds__(256)
void gemm_mma_kernel(const float* __restrict__ A, const float* __restrict__ W,
                     const float* __restrict__ bprev,
                     const float* __restrict__ outnorm, const float* __restrict__ innorm,
                     float* __restrict__ X, int M) {
    constexpr int BK = 32;
    constexpr int NCHUNK = K / BK;
    constexpr int WN = N / 2;        // warp tile cols (warps 4x2)
    constexpr int NT = WN / 8;       // n-tiles per warp (8 or 4)
    constexpr int MT = 2;            // m-tiles per warp (32 rows)
    constexpr int P = 40;            // smem pitch in bf16 (80 bytes)
    constexpr int A_HI = 0;
    constexpr int A_LO = 128 * P * 2;            // 10240
    constexpr int W_HI = 2 * A_LO;               // 20480
    constexpr int W_SZ = N * P * 2;              // 10240 / 5120
    constexpr int W_LO = W_HI + W_SZ;
    constexpr int BUFS = W_LO + W_SZ;            // bytes per buffer
    constexpr int WE = N / 8;                    // W elems per thread per chunk
    constexpr int LOGN = (N == 128) ? 7 : 6;

    extern __shared__ char smem[];
    const uint32_t sb = smem_u32(smem);
    const int tid = threadIdx.x;
    const int lane = tid & 31;
    const int wid = tid >> 5;
    const int warp_m = wid >> 1;     // 0..3
    const int warp_n = wid & 1;      // 0..1
    const int row0 = blockIdx.x * 128;

    // A-load mapping: thread -> (row, 16-col half)
    const int arow = tid & 127;
    const int ahalf = tid >> 7;
    const int grow = row0 + arow;
    const bool valid = grow < M;
    const float on  = valid ? outnorm[grow] : 0.f;
    const float inn = (MODE == 1 && valid) ? innorm[grow] : 0.f;

    // ldmatrix per-lane bases
    const int a_r = warp_m * 32 + ((lane >> 3) & 1) * 8 + (lane & 7);
    const int a_k = (lane >> 4) * 8;
    const int b_n = warp_n * WN + (lane >> 4) * 8 + (lane & 7);
    const int b_k = ((lane >> 3) & 1) * 8;

    float acc[MT][NT][4];
#pragma unroll
    for (int i = 0; i < MT; i++)
#pragma unroll
        for (int j = 0; j < NT; j++)
#pragma unroll
            for (int q = 0; q < 4; q++) acc[i][j][q] = 0.f;

    float4 av[4];
    float wv[WE];

    auto load_g = [&](int c) {
        const int kc = c * BK;
#pragma unroll
        for (int q = 0; q < 4; q++) {
            const int col = ahalf * 16 + q * 4;
            float4 v = make_float4(0.f, 0.f, 0.f, 0.f);
            if (valid) {
                v = *reinterpret_cast<const float4*>(A + (size_t)grow * K + kc + col);
                if (MODE == 0) {
                    v.x *= on; v.y *= on; v.z *= on; v.w *= on;
                } else {
                    float4 b = *reinterpret_cast<const float4*>(bprev + kc + col);
                    v.x = fmaxf(fmaf(v.x, inn, b.x), 0.f) * on;
                    v.y = fmaxf(fmaf(v.y, inn, b.y), 0.f) * on;
                    v.z = fmaxf(fmaf(v.z, inn, b.z), 0.f) * on;
                    v.w = fmaxf(fmaf(v.w, inn, b.w), 0.f) * on;
                }
            }
            av[q] = v;
        }
#pragma unroll
        for (int e = 0; e < WE; e++) {
            const int elem = tid + e * 256;
            const int n = elem & (N - 1);
            const int kk = elem >> LOGN;
            wv[e] = __ldg(W + (size_t)(kc + kk) * N + n);
        }
    };

    auto store_s = [&](int buf) {
        char* base = smem + buf * BUFS;
#pragma unroll
        for (int q = 0; q < 4; q++) {
            const int col = ahalf * 16 + q * 4;
            uint32_t h01, l01, h23, l23;
            split2(av[q].x, av[q].y, h01, l01);
            split2(av[q].z, av[q].w, h23, l23);
            const uint32_t off = (uint32_t)arow * (P * 2) + col * 2;
            *reinterpret_cast<uint2*>(base + A_HI + off) = make_uint2(h01, h23);
            *reinterpret_cast<uint2*>(base + A_LO + off) = make_uint2(l01, l23);
        }
#pragma unroll
        for (int e = 0; e < WE; e++) {
            const int elem = tid + e * 256;
            const int n = elem & (N - 1);
            const int kk = elem >> LOGN;
            uint16_t h, l;
            split1(wv[e], h, l);
            const uint32_t off = (uint32_t)n * (P * 2) + kk * 2;
            *reinterpret_cast<uint16_t*>(base + W_HI + off) = h;
            *reinterpret_cast<uint16_t*>(base + W_LO + off) = l;
        }
    };

    auto compute = [&](int buf) {
        const uint32_t ab = sb + buf * BUFS;
#pragma unroll
        for (int ks = 0; ks < 2; ks++) {
            uint32_t ah[MT][4], al[MT][4];
#pragma unroll
            for (int i = 0; i < MT; i++) {
                const uint32_t addr = ab + A_HI +
                    (uint32_t)(a_r + i * 16) * (P * 2) + (a_k + ks * 16) * 2;
                ldsm_x4(ah[i], addr);
                ldsm_x4(al[i], addr + A_LO);
            }
#pragma unroll
            for (int p = 0; p < NT / 2; p++) {
                uint32_t bh[4], bl[4];
                const uint32_t baddr = ab + W_HI +
                    (uint32_t)(b_n + p * 16) * (P * 2) + (b_k + ks * 16) * 2;
                ldsm_x4(bh, baddr);
                ldsm_x4(bl, baddr + W_SZ);
#pragma unroll
                for (int i = 0; i < MT; i++)
#pragma unroll
                    for (int jj = 0; jj < 2; jj++) {
                        float* d = acc[i][p * 2 + jj];
                        mma_bf16(d, ah[i], bh + jj * 2);
                        mma_bf16(d, ah[i], bl + jj * 2);
                        mma_bf16(d, al[i], bh + jj * 2);
                    }
            }
        }
    };

    // prologue
    load_g(0);
    store_s(0);
    __syncthreads();

    for (int c = 0; c < NCHUNK; c++) {
        if (c + 1 < NCHUNK) load_g(c + 1);       // overlap L2 latency with mma
        compute(c & 1);
        if (c + 1 < NCHUNK) store_s((c + 1) & 1);
        __syncthreads();
    }

    // epilogue: acc regs -> X
#pragma unroll
    for (int i = 0; i < MT; i++) {
        const int r0 = row0 + warp_m * 32 + i * 16 + (lane >> 2);
#pragma unroll
        for (int j = 0; j < NT; j++) {
            const int n0 = warp_n * WN + j * 8 + (lane & 3) * 2;
            if (r0 < M)
                *reinterpret_cast<float2*>(X + (size_t)r0 * N + n0) =
                    make_float2(acc[i][j][0], acc[i][j][1]);
            if (r0 + 8 < M)
                *reinterpret_cast<float2*>(X + (size_t)(r0 + 8) * N + n0) =
                    make_float2(acc[i][j][2], acc[i][j][3]);
        }
    }
}

// ------------------------------ scatter ------------------------------------

template<int D>
__global__ void scatter_kernel(const float* __restrict__ X,
                               const int* __restrict__ src, const int* __restrict__ dst,
                               float* __restrict__ AGG, int E) {
    constexpr int TPE = D / 4;
    int t = blockIdx.x * blockDim.x + threadIdx.x;
    int e = t / TPE;
    if (e >= E) return;
    int c = (t % TPE) * 4;
    int s = __ldg(src + e);
    int d = __ldg(dst + e);
    float4 v = __ldg(reinterpret_cast<const float4*>(X + (size_t)s * D + c));
    float* p = AGG + (size_t)d * D + c;
    asm volatile("red.global.add.v4.f32 [%0], {%1, %2, %3, %4};"
                 :: "l"(p), "f"(v.x), "f"(v.y), "f"(v.z), "f"(v.w)
                 : "memory");
}

// ------------------------------- pooling -----------------------------------

__device__ __forceinline__ int lower_bound_dev(const int* __restrict__ a, int n, int v) {
    int lo = 0, hi = n;
    while (lo < hi) {
        int m = (lo + hi) >> 1;
        if (a[m] < v) lo = m + 1; else hi = m;
    }
    return lo;
}

__global__ void pool_kernel(const float* __restrict__ AGG, const float* __restrict__ innorm,
                            const float* __restrict__ b3, const int* __restrict__ gids,
                            float* __restrict__ out, int Nn) {
    int g = blockIdx.x;
    int lo = lower_bound_dev(gids, Nn, g);
    int hi = lower_bound_dev(gids, Nn, g + 1);
    int f = threadIdx.x & 63;
    int slot = threadIdx.x >> 6;
    float bf = b3[f];
    float sum = 0.f;
    for (int i = lo + slot; i < hi; i += 4)
        sum += fmaf(AGG[(size_t)i * 64 + f], innorm[i], bf);
    __shared__ float sh[256];
    sh[threadIdx.x] = sum;
    __syncthreads();
    if (slot == 0) {
        float tot = sh[f] + sh[64 + f] + sh[128 + f] + sh[192 + f];
        float cnt = (float)(hi - lo);
        out[g * 64 + f] = tot / fmaxf(cnt, 1.f);
    }
}

// ------------------------------- launch ------------------------------------

extern "C" void kernel_launch(void* const* d_in, const int* in_sizes, int n_in,
                              void* d_out, int out_size) {
    const float* emb = (const float*)d_in[0];
    const float* W1  = (const float*)d_in[1];
    const float* b1  = (const float*)d_in[2];
    const float* W2  = (const float*)d_in[3];
    const float* b2  = (const float*)d_in[4];
    const float* W3  = (const float*)d_in[5];
    const float* b3  = (const float*)d_in[6];
    const int*   src = (const int*)d_in[7];
    const int*   dst = (const int*)d_in[8];
    const int*   gid = (const int*)d_in[9];
    float* out = (float*)d_out;

    const int Nn = in_sizes[0] / 128;   // 100000
    const int E  = in_sizes[7];         // 1600000
    const int G  = out_size / 64;       // 64

    float *X, *AGG, *onrm, *inrm;
    cudaGetSymbolAddress((void**)&X,    g_X);
    cudaGetSymbolAddress((void**)&AGG,  g_AGG);
    cudaGetSymbolAddress((void**)&onrm, g_outnorm);
    cudaGetSymbolAddress((void**)&inrm, g_innorm);

    // dynamic smem: 2 * (A hi/lo 20480 + W hi/lo 2*N*80)
    const int smem128 = 2 * (20480 + 2 * 128 * 80);  // 81920
    const int smem64  = 2 * (20480 + 2 * 64 * 80);   // 61440
    cudaFuncSetAttribute(gemm_mma_kernel<128, 128, 0>,
                         cudaFuncAttributeMaxDynamicSharedMemorySize, smem128);
    cudaFuncSetAttribute(gemm_mma_kernel<128, 64, 1>,
                         cudaFuncAttributeMaxDynamicSharedMemorySize, smem64);
    cudaFuncSetAttribute(gemm_mma_kernel<64, 64, 1>,
                         cudaFuncAttributeMaxDynamicSharedMemorySize, smem64);

    const int T = 256;
    const int gemm_grid = (Nn + 127) / 128;

    // degrees -> norms
    zero_kernel<<<(Nn / 4 + T - 1) / T, T>>>(onrm, Nn / 4);
    zero_kernel<<<(Nn / 4 + T - 1) / T, T>>>(inrm, Nn / 4);
    degree_kernel<<<(E + T - 1) / T, T>>>(src, dst, onrm, inrm, E);
    norm_kernel<<<(Nn + T - 1) / T, T>>>(onrm, inrm, Nn);

    // Layer 1: X1 = (emb * outnorm) @ W1
    gemm_mma_kernel<128, 128, 0><<<gemm_grid, T, smem128>>>(emb, W1, nullptr, onrm, inrm, X, Nn);
    zero_kernel<<<(Nn * 128 / 4 + T - 1) / T, T>>>(AGG, Nn * 128 / 4);
    scatter_kernel<128><<<(int)(((long)E * 32 + T - 1) / T), T>>>(X, src, dst, AGG, E);

    // Layer 2: X2 = relu(agg1*innorm + b1)*outnorm @ W2
    gemm_mma_kernel<128, 64, 1><<<gemm_grid, T, smem64>>>(AGG, W2, b1, onrm, inrm, X, Nn);
    zero_kernel<<<(Nn * 64 / 4 + T - 1) / T, T>>>(AGG, Nn * 64 / 4);
    scatter_kernel<64><<<(int)(((long)E * 16 + T - 1) / T), T>>>(X, src, dst, AGG, E);

    // Layer 3: X3 = relu(agg2*innorm + b2)*outnorm @ W3
    gemm_mma_kernel<64, 64, 1><<<gemm_grid, T, smem64>>>(AGG, W3, b2, onrm, inrm, X, Nn);
    zero_kernel<<<(Nn * 64 / 4 + T - 1) / T, T>>>(AGG, Nn * 64 / 4);
    scatter_kernel<64><<<(int)(((long)E * 16 + T - 1) / T), T>>>(X, src, dst, AGG, E);

    // Pool
    pool_kernel<<<G, T>>>(AGG, inrm, b3, gid, out, Nn);
}

// round 5
// speedup vs baseline: 1.8400x; 1.7471x over previous
#include <cuda_runtime.h>
#include <cuda_bf16.h>
#include <cstdint>

// ---------------------------------------------------------------------------
// GCN: 3x (pointwise -> bf16x3 mma.sync GEMM -> CSR gather-sum) + mean pool
// GEMM first (row scaling commutes with @W; segment-sum is linear).
// Aggregation is PULL-based over a per-launch CSR (dst-sorted edges):
// no global atomics in the hot path, AGG rows written exactly once.
// ---------------------------------------------------------------------------

#define MAX_NODES 100000
#define MAX_EDGES 1600000
#define MAX_FEATS 128
#define SCAN_BS 512

__device__ float g_X[MAX_NODES * MAX_FEATS];    // GEMM outputs (pre-gather)
__device__ float g_AGG[MAX_NODES * MAX_FEATS];  // gathered sums
__device__ float g_outnorm[MAX_NODES];
__device__ float g_innorm[MAX_NODES];
__device__ int   g_indeg[MAX_NODES];
__device__ int   g_outdeg[MAX_NODES];
__device__ int   g_rowptr[MAX_NODES + 1];
__device__ int   g_fill[MAX_NODES];
__device__ int   g_col[MAX_EDGES];
__device__ int   g_bsums[(MAX_NODES + SCAN_BS - 1) / SCAN_BS];

// ----------------------------- helpers -------------------------------------

__device__ __forceinline__ uint32_t smem_u32(const void* p) {
    uint32_t a;
    asm("{ .reg .u64 t; cvta.to.shared.u64 t, %1; cvt.u32.u64 %0, t; }" : "=r"(a) : "l"(p));
    return a;
}

__device__ __forceinline__ void ldsm_x4(uint32_t* r, uint32_t addr) {
    asm volatile("ldmatrix.sync.aligned.m8n8.x4.shared.b16 {%0,%1,%2,%3}, [%4];"
                 : "=r"(r[0]), "=r"(r[1]), "=r"(r[2]), "=r"(r[3]) : "r"(addr));
}

__device__ __forceinline__ void mma_bf16(float* d, const uint32_t* a, const uint32_t* b) {
    asm volatile("mma.sync.aligned.m16n8k16.row.col.f32.bf16.bf16.f32 "
                 "{%0,%1,%2,%3}, {%4,%5,%6,%7}, {%8,%9}, {%0,%1,%2,%3};"
                 : "+f"(d[0]), "+f"(d[1]), "+f"(d[2]), "+f"(d[3])
                 : "r"(a[0]), "r"(a[1]), "r"(a[2]), "r"(a[3]), "r"(b[0]), "r"(b[1]));
}

__device__ __forceinline__ void split2(float x, float y, uint32_t& hi, uint32_t& lo) {
    __nv_bfloat162 h = __floats2bfloat162_rn(x, y);
    float rx = x - __bfloat162float(h.x);
    float ry = y - __bfloat162float(h.y);
    __nv_bfloat162 l = __floats2bfloat162_rn(rx, ry);
    hi = reinterpret_cast<uint32_t&>(h);
    lo = reinterpret_cast<uint32_t&>(l);
}

__device__ __forceinline__ void split1(float x, uint16_t& hi, uint16_t& lo) {
    __nv_bfloat16 h = __float2bfloat16_rn(x);
    float r = x - __bfloat162float(h);
    __nv_bfloat16 l = __float2bfloat16_rn(r);
    hi = reinterpret_cast<uint16_t&>(h);
    lo = reinterpret_cast<uint16_t&>(l);
}

// --------------------------- CSR construction ------------------------------

__global__ void zero_int2_kernel(int* __restrict__ a, int* __restrict__ b, int n) {
    int i = blockIdx.x * blockDim.x + threadIdx.x;
    if (i < n) { a[i] = 0; b[i] = 0; }
}

__global__ void hist_kernel(const int* __restrict__ src, const int* __restrict__ dst,
                            int* __restrict__ outdeg, int* __restrict__ indeg, int E) {
    int i = blockIdx.x * blockDim.x + threadIdx.x;
    if (i < E) {
        atomicAdd(outdeg + src[i], 1);
        atomicAdd(indeg + dst[i], 1);
    }
}

// Phase A: per-block inclusive scan of indeg -> rowptr holds exclusive-in-block
__global__ void scanA_kernel(const int* __restrict__ deg, int* __restrict__ rowptr,
                             int* __restrict__ bsums, int n) {
    __shared__ int sh[SCAN_BS];
    int t = threadIdx.x;
    int i = blockIdx.x * SCAN_BS + t;
    int v = (i < n) ? deg[i] : 0;
    sh[t] = v;
    __syncthreads();
#pragma unroll
    for (int off = 1; off < SCAN_BS; off <<= 1) {
        int x = (t >= off) ? sh[t - off] : 0;
        __syncthreads();
        sh[t] += x;
        __syncthreads();
    }
    if (i < n) rowptr[i] = sh[t] - v;
    if (t == SCAN_BS - 1) bsums[blockIdx.x] = sh[t];
}

// Phase B: single-block exclusive scan of block sums (nb <= 256)
__global__ void scanB_kernel(int* __restrict__ bsums, int nb) {
    __shared__ int sh[256];
    int t = threadIdx.x;
    int v = (t < nb) ? bsums[t] : 0;
    sh[t] = v;
    __syncthreads();
#pragma unroll
    for (int off = 1; off < 256; off <<= 1) {
        int x = (t >= off) ? sh[t - off] : 0;
        __syncthreads();
        sh[t] += x;
        __syncthreads();
    }
    if (t < nb) bsums[t] = sh[t] - v;
}

// Phase C: add block offsets; copy to fill cursors; set rowptr[n] = E
__global__ void scanC_kernel(int* __restrict__ rowptr, int* __restrict__ fill,
                             const int* __restrict__ bsums, int n, int E) {
    int i = blockIdx.x * blockDim.x + threadIdx.x;
    if (i < n) {
        int r = rowptr[i] + bsums[i / SCAN_BS];
        rowptr[i] = r;
        fill[i] = r;
    }
    if (i == 0) rowptr[n] = E;
}

__global__ void fill_kernel(const int* __restrict__ src, const int* __restrict__ dst,
                            int* __restrict__ fill, int* __restrict__ col, int E) {
    int i = blockIdx.x * blockDim.x + threadIdx.x;
    if (i < E) {
        int p = atomicAdd(fill + dst[i], 1);
        col[p] = src[i];
    }
}

__global__ void norm_kernel(const int* __restrict__ od, const int* __restrict__ id,
                            float* __restrict__ onrm, float* __restrict__ inrm, int n) {
    int i = blockIdx.x * blockDim.x + threadIdx.x;
    if (i < n) {
        onrm[i] = rsqrtf(fmaxf((float)od[i], 1.0f));
        inrm[i] = rsqrtf(fmaxf((float)id[i], 1.0f));
    }
}

// --------------------------- bf16x3 GEMM -----------------------------------
// X[M,N] = f(A[M,K]) @ W[K,N], CTA tile 128 x N, K chunks of 32, 256 threads.
// MODE 0: f(a)[r,k] = a[r,k] * outnorm[r]
// MODE 1: f(a)[r,k] = relu(a[r,k]*innorm[r] + bprev[k]) * outnorm[r]
// bf16x3: D = Ah@Bh + Ah@Bl + Al@Bh, fp32 accum (mma.sync m16n8k16).

template<int K, int N, int MODE>
__global__ __launch_bounds__(256)
void gemm_mma_kernel(const float* __restrict__ A, const float* __restrict__ W,
                     const float* __restrict__ bprev,
                     const float* __restrict__ outnorm, const float* __restrict__ innorm,
                     float* __restrict__ X, int M) {
    constexpr int BK = 32;
    constexpr int NCHUNK = K / BK;
    constexpr int WN = N / 2;
    constexpr int NT = WN / 8;
    constexpr int MT = 2;
    constexpr int P = 40;            // smem pitch in bf16 (80B, LDSM-clean)
    constexpr int A_HI = 0;
    constexpr int A_LO = 128 * P * 2;
    constexpr int W_HI = 2 * A_LO;
    constexpr int W_SZ = N * P * 2;
    constexpr int W_LO = W_HI + W_SZ;
    constexpr int BUFS = W_LO + W_SZ;
    constexpr int WE = N / 8;
    constexpr int LOGN = (N == 128) ? 7 : 6;

    extern __shared__ char smem[];
    const uint32_t sb = smem_u32(smem);
    const int tid = threadIdx.x;
    const int lane = tid & 31;
    const int wid = tid >> 5;
    const int warp_m = wid >> 1;
    const int warp_n = wid & 1;
    const int row0 = blockIdx.x * 128;

    const int arow = tid & 127;
    const int ahalf = tid >> 7;
    const int grow = row0 + arow;
    const bool valid = grow < M;
    const float on  = valid ? outnorm[grow] : 0.f;
    const float inn = (MODE == 1 && valid) ? innorm[grow] : 0.f;

    const int a_r = warp_m * 32 + ((lane >> 3) & 1) * 8 + (lane & 7);
    const int a_k = (lane >> 4) * 8;
    const int b_n = warp_n * WN + (lane >> 4) * 8 + (lane & 7);
    const int b_k = ((lane >> 3) & 1) * 8;

    float acc[MT][NT][4];
#pragma unroll
    for (int i = 0; i < MT; i++)
#pragma unroll
        for (int j = 0; j < NT; j++)
#pragma unroll
            for (int q = 0; q < 4; q++) acc[i][j][q] = 0.f;

    float4 av[4];
    float wv[WE];

    auto load_g = [&](int c) {
        const int kc = c * BK;
#pragma unroll
        for (int q = 0; q < 4; q++) {
            const int col = ahalf * 16 + q * 4;
            float4 v = make_float4(0.f, 0.f, 0.f, 0.f);
            if (valid) {
                v = *reinterpret_cast<const float4*>(A + (size_t)grow * K + kc + col);
                if (MODE == 0) {
                    v.x *= on; v.y *= on; v.z *= on; v.w *= on;
                } else {
                    float4 b = *reinterpret_cast<const float4*>(bprev + kc + col);
                    v.x = fmaxf(fmaf(v.x, inn, b.x), 0.f) * on;
                    v.y = fmaxf(fmaf(v.y, inn, b.y), 0.f) * on;
                    v.z = fmaxf(fmaf(v.z, inn, b.z), 0.f) * on;
                    v.w = fmaxf(fmaf(v.w, inn, b.w), 0.f) * on;
                }
            }
            av[q] = v;
        }
#pragma unroll
        for (int e = 0; e < WE; e++) {
            const int elem = tid + e * 256;
            const int n = elem & (N - 1);
            const int kk = elem >> LOGN;
            wv[e] = __ldg(W + (size_t)(kc + kk) * N + n);
        }
    };

    auto store_s = [&](int buf) {
        char* base = smem + buf * BUFS;
#pragma unroll
        for (int q = 0; q < 4; q++) {
            const int col = ahalf * 16 + q * 4;
            uint32_t h01, l01, h23, l23;
            split2(av[q].x, av[q].y, h01, l01);
            split2(av[q].z, av[q].w, h23, l23);
            const uint32_t off = (uint32_t)arow * (P * 2) + col * 2;
            *reinterpret_cast<uint2*>(base + A_HI + off) = make_uint2(h01, h23);
            *reinterpret_cast<uint2*>(base + A_LO + off) = make_uint2(l01, l23);
        }
#pragma unroll
        for (int e = 0; e < WE; e++) {
            const int elem = tid + e * 256;
            const int n = elem & (N - 1);
            const int kk = elem >> LOGN;
            uint16_t h, l;
            split1(wv[e], h, l);
            const uint32_t off = (uint32_t)n * (P * 2) + kk * 2;
            *reinterpret_cast<uint16_t*>(base + W_HI + off) = h;
            *reinterpret_cast<uint16_t*>(base + W_LO + off) = l;
        }
    };

    auto compute = [&](int buf) {
        const uint32_t ab = sb + buf * BUFS;
#pragma unroll
        for (int ks = 0; ks < 2; ks++) {
            uint32_t ah[MT][4], al[MT][4];
#pragma unroll
            for (int i = 0; i < MT; i++) {
                const uint32_t addr = ab + A_HI +
                    (uint32_t)(a_r + i * 16) * (P * 2) + (a_k + ks * 16) * 2;
                ldsm_x4(ah[i], addr);
                ldsm_x4(al[i], addr + A_LO);
            }
#pragma unroll
            for (int p = 0; p < NT / 2; p++) {
                uint32_t bh[4], bl[4];
                const uint32_t baddr = ab + W_HI +
                    (uint32_t)(b_n + p * 16) * (P * 2) + (b_k + ks * 16) * 2;
                ldsm_x4(bh, baddr);
                ldsm_x4(bl, baddr + W_SZ);
#pragma unroll
                for (int i = 0; i < MT; i++)
#pragma unroll
                    for (int jj = 0; jj < 2; jj++) {
                        float* d = acc[i][p * 2 + jj];
                        mma_bf16(d, ah[i], bh + jj * 2);
                        mma_bf16(d, ah[i], bl + jj * 2);
                        mma_bf16(d, al[i], bh + jj * 2);
                    }
            }
        }
    };

    load_g(0);
    store_s(0);
    __syncthreads();

    for (int c = 0; c < NCHUNK; c++) {
        if (c + 1 < NCHUNK) load_g(c + 1);
        compute(c & 1);
        if (c + 1 < NCHUNK) store_s((c + 1) & 1);
        __syncthreads();
    }

#pragma unroll
    for (int i = 0; i < MT; i++) {
        const int r0 = row0 + warp_m * 32 + i * 16 + (lane >> 2);
#pragma unroll
        for (int j = 0; j < NT; j++) {
            const int n0 = warp_n * WN + j * 8 + (lane & 3) * 2;
            if (r0 < M)
                *reinterpret_cast<float2*>(X + (size_t)r0 * N + n0) =
                    make_float2(acc[i][j][0], acc[i][j][1]);
            if (r0 + 8 < M)
                *reinterpret_cast<float2*>(X + (size_t)(r0 + 8) * N + n0) =
                    make_float2(acc[i][j][2], acc[i][j][3]);
        }
    }
}

// ------------------------------ CSR gather ---------------------------------
// AGG[n] = sum over e in [rowptr[n], rowptr[n+1]) of X[col[e]]
// D/4 lanes per node, one float4 per lane; 2-edge unrolled for MLP.

template<int D>
__global__ __launch_bounds__(256)
void gather_kernel(const float* __restrict__ X, const int* __restrict__ rowptr,
                   const int* __restrict__ col, float* __restrict__ AGG, int Nn) {
    constexpr int LPN = D / 4;
    int t = blockIdx.x * blockDim.x + threadIdx.x;
    int node = t / LPN;
    if (node >= Nn) return;
    int c = (t % LPN) * 4;
    int beg = __ldg(rowptr + node);
    int end = __ldg(rowptr + node + 1);
    float4 acc = make_float4(0.f, 0.f, 0.f, 0.f);
    int e = beg;
    for (; e + 1 < end; e += 2) {
        int s0 = __ldg(col + e);
        int s1 = __ldg(col + e + 1);
        float4 v0 = __ldg(reinterpret_cast<const float4*>(X + (size_t)s0 * D + c));
        float4 v1 = __ldg(reinterpret_cast<const float4*>(X + (size_t)s1 * D + c));
        acc.x += v0.x; acc.y += v0.y; acc.z += v0.z; acc.w += v0.w;
        acc.x += v1.x; acc.y += v1.y; acc.z += v1.z; acc.w += v1.w;
    }
    if (e < end) {
        int s0 = __ldg(col + e);
        float4 v0 = __ldg(reinterpret_cast<const float4*>(X + (size_t)s0 * D + c));
        acc.x += v0.x; acc.y += v0.y; acc.z += v0.z; acc.w += v0.w;
    }
    *reinterpret_cast<float4*>(AGG + (size_t)node * D + c) = acc;
}

// ------------------------------- pooling -----------------------------------

__device__ __forceinline__ int lower_bound_dev(const int* __restrict__ a, int n, int v) {
    int lo = 0, hi = n;
    while (lo < hi) {
        int m = (lo + hi) >> 1;
        if (a[m] < v) lo = m + 1; else hi = m;
    }
    return lo;
}

__global__ void pool_kernel(const float* __restrict__ AGG, const float* __restrict__ innorm,
                            const float* __restrict__ b3, const int* __restrict__ gids,
                            float* __restrict__ out, int Nn) {
    int g = blockIdx.x;
    int lo = lower_bound_dev(gids, Nn, g);
    int hi = lower_bound_dev(gids, Nn, g + 1);
    int f = threadIdx.x & 63;
    int slot = threadIdx.x >> 6;
    float bf = b3[f];
    float sum = 0.f;
    for (int i = lo + slot; i < hi; i += 4)
        sum += fmaf(AGG[(size_t)i * 64 + f], innorm[i], bf);
    __shared__ float sh[256];
    sh[threadIdx.x] = sum;
    __syncthreads();
    if (slot == 0) {
        float tot = sh[f] + sh[64 + f] + sh[128 + f] + sh[192 + f];
        float cnt = (float)(hi - lo);
        out[g * 64 + f] = tot / fmaxf(cnt, 1.f);
    }
}

// ------------------------------- launch ------------------------------------

extern "C" void kernel_launch(void* const* d_in, const int* in_sizes, int n_in,
                              void* d_out, int out_size) {
    const float* emb = (const float*)d_in[0];
    const float* W1  = (const float*)d_in[1];
    const float* b1  = (const float*)d_in[2];
    const float* W2  = (const float*)d_in[3];
    const float* b2  = (const float*)d_in[4];
    const float* W3  = (const float*)d_in[5];
    const float* b3  = (const float*)d_in[6];
    const int*   src = (const int*)d_in[7];
    const int*   dst = (const int*)d_in[8];
    const int*   gid = (const int*)d_in[9];
    float* out = (float*)d_out;

    const int Nn = in_sizes[0] / 128;   // 100000
    const int E  = in_sizes[7];         // 1600000
    const int G  = out_size / 64;       // 64

    float *X, *AGG, *onrm, *inrm;
    int *indeg, *outdeg, *rowptr, *fillc, *colA, *bsums;
    cudaGetSymbolAddress((void**)&X,      g_X);
    cudaGetSymbolAddress((void**)&AGG,    g_AGG);
    cudaGetSymbolAddress((void**)&onrm,   g_outnorm);
    cudaGetSymbolAddress((void**)&inrm,   g_innorm);
    cudaGetSymbolAddress((void**)&indeg,  g_indeg);
    cudaGetSymbolAddress((void**)&outdeg, g_outdeg);
    cudaGetSymbolAddress((void**)&rowptr, g_rowptr);
    cudaGetSymbolAddress((void**)&fillc,  g_fill);
    cudaGetSymbolAddress((void**)&colA,   g_col);
    cudaGetSymbolAddress((void**)&bsums,  g_bsums);

    const int smem128 = 2 * (20480 + 2 * 128 * 80);  // 81920
    const int smem64  = 2 * (20480 + 2 * 64 * 80);   // 61440
    cudaFuncSetAttribute(gemm_mma_kernel<128, 128, 0>,
                         cudaFuncAttributeMaxDynamicSharedMemorySize, smem128);
    cudaFuncSetAttribute(gemm_mma_kernel<128, 64, 1>,
                         cudaFuncAttributeMaxDynamicSharedMemorySize, smem64);
    cudaFuncSetAttribute(gemm_mma_kernel<64, 64, 1>,
                         cudaFuncAttributeMaxDynamicSharedMemorySize, smem64);

    const int T = 256;
    const int gemm_grid = (Nn + 127) / 128;
    const int nb_scan = (Nn + SCAN_BS - 1) / SCAN_BS;

    // ---- CSR build + norms ----
    zero_int2_kernel<<<(Nn + T - 1) / T, T>>>(indeg, outdeg, Nn);
    hist_kernel<<<(E + T - 1) / T, T>>>(src, dst, outdeg, indeg, E);
    scanA_kernel<<<nb_scan, SCAN_BS>>>(indeg, rowptr, bsums, Nn);
    scanB_kernel<<<1, 256>>>(bsums, nb_scan);
    scanC_kernel<<<(Nn + T - 1) / T, T>>>(rowptr, fillc, bsums, Nn, E);
    norm_kernel<<<(Nn + T - 1) / T, T>>>(outdeg, indeg, onrm, inrm, Nn);
    fill_kernel<<<(E + T - 1) / T, T>>>(src, dst, fillc, colA, E);

    // Layer 1: X1 = (emb * outnorm) @ W1 ; agg1 = gather(X1)
    gemm_mma_kernel<128, 128, 0><<<gemm_grid, T, smem128>>>(emb, W1, nullptr, onrm, inrm, X, Nn);
    gather_kernel<128><<<(Nn * 32 + T - 1) / T, T>>>(X, rowptr, colA, AGG, Nn);

    // Layer 2: X2 = relu(agg1*innorm + b1)*outnorm @ W2 ; agg2 = gather(X2)
    gemm_mma_kernel<128, 64, 1><<<gemm_grid, T, smem64>>>(AGG, W2, b1, onrm, inrm, X, Nn);
    gather_kernel<64><<<(Nn * 16 + T - 1) / T, T>>>(X, rowptr, colA, AGG, Nn);

    // Layer 3: X3 = relu(agg2*innorm + b2)*outnorm @ W3 ; agg3 = gather(X3)
    gemm_mma_kernel<64, 64, 1><<<gemm_grid, T, smem64>>>(AGG, W3, b2, onrm, inrm, X, Nn);
    gather_kernel<64><<<(Nn * 16 + T - 1) / T, T>>>(X, rowptr, colA, AGG, Nn);

    // Pool
    pool_kernel<<<G, T>>>(AGG, inrm, b3, gid, out, Nn);
}